// round 13
// baseline (speedup 1.0000x reference)
#include <cuda_runtime.h>
#include <math.h>

#define BB 64
#define SS 4096
#define DD 256
#define SPLIT 32
#define ROWS_PER_CHUNK (SS / SPLIT)          // 128 rows per block
#define ROWS_PER_WARP  (ROWS_PER_CHUNK / 8)  // 16 rows per warp
#define NCHUNK (BB * SPLIT)                  // 2048

// Scratch partials (no allocation allowed in kernel_launch)
__device__ float g_m[NCHUNK];
__device__ float g_z[NCHUNK];
__device__ float g_acc[NCHUNK * DD];

// ---------------------------------------------------------------------------
// Kernel 1: fused LN-score + online-softmax weighted accumulation.
// Software-pipelined: while updating acc with row r, the butterfly reduction
// of row r+1 and the loads of row r+2 are in flight (3 rotating row buffers).
// (UNCHANGED from R12 — protected win.)
// ---------------------------------------------------------------------------
__global__ __launch_bounds__(256, 4) void fused_kernel(
    const float* __restrict__ x, const float* __restrict__ mask,
    const float* __restrict__ gamma, const float* __restrict__ beta,
    const float* __restrict__ w, const float* __restrict__ bias)
{
    const int chunk = blockIdx.x;            // 0..2047
    const int b     = chunk / SPLIT;
    const int k     = chunk % SPLIT;
    const int wid   = threadIdx.x >> 5;      // 0..7
    const int lane  = threadIdx.x & 31;
    const int d0    = lane * 8;

    const int s_base = k * ROWS_PER_CHUNK + wid * ROWS_PER_WARP;
    const float* xrow = x + ((size_t)b * SS + s_base) * DD;
    const float* mrow = mask + (size_t)b * SS + s_base;

    // ---- per-lane parameter setup (once) ----
    const float4 g1 = *(const float4*)(gamma + d0);
    const float4 g2 = *(const float4*)(gamma + d0 + 4);
    const float4 w1 = *(const float4*)(w + d0);
    const float4 w2 = *(const float4*)(w + d0 + 4);
    const float4 b1 = *(const float4*)(beta + d0);
    const float4 b2 = *(const float4*)(beta + d0 + 4);

    float gw[8];
    gw[0] = g1.x * w1.x; gw[1] = g1.y * w1.y; gw[2] = g1.z * w1.z; gw[3] = g1.w * w1.w;
    gw[4] = g2.x * w2.x; gw[5] = g2.y * w2.y; gw[6] = g2.z * w2.z; gw[7] = g2.w * w2.w;

    float sgw = gw[0]+gw[1]+gw[2]+gw[3]+gw[4]+gw[5]+gw[6]+gw[7];
    float sbw = b1.x*w1.x + b1.y*w1.y + b1.z*w1.z + b1.w*w1.w
              + b2.x*w2.x + b2.y*w2.y + b2.z*w2.z + b2.w*w2.w;
    #pragma unroll
    for (int o = 16; o > 0; o >>= 1) {
        sgw += __shfl_xor_sync(~0u, sgw, o);
        sbw += __shfl_xor_sync(~0u, sbw, o);
    }
    const float cterm = sbw + bias[0];

    // Preload this warp's 16 mask values into lanes 0..15 (off the hot path)
    const float mval = (lane < ROWS_PER_WARP) ? mrow[lane] : 0.0f;

    // ---- pipelined online softmax accumulation over 16 rows ----
    float acc[8];
    #pragma unroll
    for (int j = 0; j < 8; j++) acc[j] = 0.0f;
    float m = -INFINITY, Z = 0.0f;

    float4 xa[3], xc[3];                      // rotating row buffers
    xa[0] = *(const float4*)(xrow + d0);
    xc[0] = *(const float4*)(xrow + d0 + 4);
    xa[1] = *(const float4*)(xrow + DD + d0);
    xc[1] = *(const float4*)(xrow + DD + d0 + 4);

    // reduce row 0 (current reduction results)
    float rsx, rsx2, rsxgw;
    {
        const float4 a = xa[0], c = xc[0];
        float sx   = a.x + a.y + a.z + a.w + c.x + c.y + c.z + c.w;
        float sx2  = a.x*a.x + a.y*a.y + a.z*a.z + a.w*a.w
                   + c.x*c.x + c.y*c.y + c.z*c.z + c.w*c.w;
        float sxgw = a.x*gw[0] + a.y*gw[1] + a.z*gw[2] + a.w*gw[3]
                   + c.x*gw[4] + c.y*gw[5] + c.z*gw[6] + c.w*gw[7];
        #pragma unroll
        for (int o = 16; o > 0; o >>= 1) {
            sx   += __shfl_xor_sync(~0u, sx,   o);
            sx2  += __shfl_xor_sync(~0u, sx2,  o);
            sxgw += __shfl_xor_sync(~0u, sxgw, o);
        }
        rsx = sx; rsx2 = sx2; rsxgw = sxgw;
    }

    #pragma unroll
    for (int r = 0; r < ROWS_PER_WARP; r++) {
        // stage 1: issue loads for row r+2
        if (r + 2 < ROWS_PER_WARP) {
            xa[(r + 2) % 3] = *(const float4*)(xrow + (size_t)(r + 2) * DD + d0);
            xc[(r + 2) % 3] = *(const float4*)(xrow + (size_t)(r + 2) * DD + d0 + 4);
        }

        // stage 2: butterfly-reduce row r+1 (independent of stage 3)
        float nsx = 0.0f, nsx2 = 0.0f, nsxgw = 0.0f;
        if (r + 1 < ROWS_PER_WARP) {
            const float4 a = xa[(r + 1) % 3], c = xc[(r + 1) % 3];
            nsx   = a.x + a.y + a.z + a.w + c.x + c.y + c.z + c.w;
            nsx2  = a.x*a.x + a.y*a.y + a.z*a.z + a.w*a.w
                  + c.x*c.x + c.y*c.y + c.z*c.z + c.w*c.w;
            nsxgw = a.x*gw[0] + a.y*gw[1] + a.z*gw[2] + a.w*gw[3]
                  + c.x*gw[4] + c.y*gw[5] + c.z*gw[6] + c.w*gw[7];
            #pragma unroll
            for (int o = 16; o > 0; o >>= 1) {
                nsx   += __shfl_xor_sync(~0u, nsx,   o);
                nsx2  += __shfl_xor_sync(~0u, nsx2,  o);
                nsxgw += __shfl_xor_sync(~0u, nsxgw, o);
            }
        }

        // stage 3: score + online update for row r (uses last iter's reduction)
        {
            const float mk  = __shfl_sync(~0u, mval, r);
            const float mu  = rsx * (1.0f / DD);
            const float var = rsx2 * (1.0f / DD) - mu * mu;
            const float rs  = rsqrtf(var + 1e-3f);
            float score = rs * (rsxgw - mu * sgw) + cterm;
            score += (1.0f - mk) * -1e9f;

            // single-exp online update: one of {sc, p} is exactly 1
            const float dlt = score - m;                 // +inf on first iter
            const bool  up  = dlt > 0.0f;
            const float e   = __expf(up ? -dlt : dlt);   // exp(-|dlt|); 0 first iter
            const float sc  = up ? e : 1.0f;
            const float p   = up ? 1.0f : e;
            if (up) m = score;

            const float4 a = xa[r % 3], c = xc[r % 3];
            Z = Z * sc + p;
            acc[0] = acc[0] * sc + p * a.x;
            acc[1] = acc[1] * sc + p * a.y;
            acc[2] = acc[2] * sc + p * a.z;
            acc[3] = acc[3] * sc + p * a.w;
            acc[4] = acc[4] * sc + p * c.x;
            acc[5] = acc[5] * sc + p * c.y;
            acc[6] = acc[6] * sc + p * c.z;
            acc[7] = acc[7] * sc + p * c.w;
        }

        rsx = nsx; rsx2 = nsx2; rsxgw = nsxgw;
    }

    // ---- block-level combine of the 8 warp partials ----
    __shared__ float s_m[8];
    __shared__ float s_z[8];
    __shared__ float s_acc[8][DD];

    if (lane == 0) { s_m[wid] = m; s_z[wid] = Z; }
    __syncthreads();

    float M = s_m[0];
    #pragma unroll
    for (int t = 1; t < 8; t++) M = fmaxf(M, s_m[t]);

    const float myscale = __expf(m - M);
    #pragma unroll
    for (int j = 0; j < 8; j++) s_acc[wid][d0 + j] = acc[j] * myscale;
    __syncthreads();

    const int t = threadIdx.x;
    float asum = 0.0f;
    #pragma unroll
    for (int ww = 0; ww < 8; ww++) asum += s_acc[ww][t];
    g_acc[(size_t)chunk * DD + t] = asum;

    if (t == 0) {
        float Zb = 0.0f;
        #pragma unroll
        for (int ww = 0; ww < 8; ww++) Zb += s_z[ww] * __expf(s_m[ww] - M);
        g_m[chunk] = M;
        g_z[chunk] = Zb;
    }
}

// ---------------------------------------------------------------------------
// Kernel 2: deterministic 32-way combine per batch -> out [B, D].
// Grid (4, BB): block q owns 64 columns of batch b. 256 threads =
// 4 groups x 64 columns; group g sums chunks 8g..8g+7, then the fixed-order
// 4-way group sum (p0+p1)+(p2+p3) — identical summation order kk=0..31.
// ---------------------------------------------------------------------------
__global__ __launch_bounds__(256) void combine_kernel(float* __restrict__ out)
{
    const int q = blockIdx.x;            // 0..3 column quarter
    const int b = blockIdx.y;            // batch
    const int g = threadIdx.x >> 6;      // 0..3 chunk group
    const int d = q * 64 + (threadIdx.x & 63);   // column 0..255

    __shared__ float s_m[SPLIT];
    __shared__ float s_z[SPLIT];
    __shared__ float s_sc[SPLIT];
    __shared__ float s_part[4][64];

    if (threadIdx.x < SPLIT) {
        s_m[threadIdx.x] = g_m[b * SPLIT + threadIdx.x];
        s_z[threadIdx.x] = g_z[b * SPLIT + threadIdx.x];
    }
    __syncthreads();

    float M = s_m[0];
    #pragma unroll
    for (int kk = 1; kk < SPLIT; kk++) M = fmaxf(M, s_m[kk]);

    if (threadIdx.x < SPLIT) s_sc[threadIdx.x] = __expf(s_m[threadIdx.x] - M);
    __syncthreads();

    // group g sums chunks kk = 8g .. 8g+7 for its column d (coalesced, MLP=8)
    float asum = 0.0f;
    #pragma unroll
    for (int j = 0; j < 8; j++) {
        const int kk = g * 8 + j;
        asum += g_acc[(size_t)(b * SPLIT + kk) * DD + d] * s_sc[kk];
    }
    s_part[g][threadIdx.x & 63] = asum;
    __syncthreads();

    if (g == 0) {
        // Z total: fixed order kk=0..31, computed redundantly per thread
        float zsum = 0.0f;
        #pragma unroll
        for (int kk = 0; kk < SPLIT; kk++) zsum += s_z[kk] * s_sc[kk];

        const int dd = threadIdx.x & 63;
        const float total = ((s_part[0][dd] + s_part[1][dd])
                           + (s_part[2][dd] + s_part[3][dd]));
        out[b * DD + d] = total / zsum;
    }
}

// ---------------------------------------------------------------------------
extern "C" void kernel_launch(void* const* d_in, const int* in_sizes, int n_in,
                              void* d_out, int out_size)
{
    const float* x     = (const float*)d_in[0];
    const float* mask  = (const float*)d_in[1];
    const float* gamma = (const float*)d_in[2];
    const float* beta  = (const float*)d_in[3];
    const float* w     = (const float*)d_in[4];
    const float* bias  = (const float*)d_in[5];
    float* out = (float*)d_out;

    fused_kernel<<<NCHUNK, 256>>>(x, mask, gamma, beta, w, bias);

    dim3 gc(4, BB);
    combine_kernel<<<gc, 256>>>(out);
}

// round 15
// speedup vs baseline: 1.0321x; 1.0321x over previous
#include <cuda_runtime.h>
#include <math.h>

#define BB 64
#define SS 4096
#define DD 256
#define SPLIT 32
#define ROWS_PER_CHUNK (SS / SPLIT)          // 128 rows per block
#define ROWS_PER_WARP  (ROWS_PER_CHUNK / 8)  // 16 rows per warp
#define NCHUNK (BB * SPLIT)                  // 2048

// Scratch partials (no allocation allowed in kernel_launch)
__device__ float g_m[NCHUNK];
__device__ float g_z[NCHUNK];
__device__ float g_acc[NCHUNK * DD];
__device__ int   g_cnt[BB];                  // zero-init; self-resetting

// ---------------------------------------------------------------------------
// Fused kernel: LN-score + online-softmax weighted accumulation (R12 mainloop,
// unchanged) + last-block-done combine with SINGLE-THREAD fences.
// ---------------------------------------------------------------------------
__global__ __launch_bounds__(256, 4) void fused_kernel(
    const float* __restrict__ x, const float* __restrict__ mask,
    const float* __restrict__ gamma, const float* __restrict__ beta,
    const float* __restrict__ w, const float* __restrict__ bias,
    float* __restrict__ out)
{
    const int chunk = blockIdx.x;            // 0..2047
    const int b     = chunk / SPLIT;
    const int k     = chunk % SPLIT;
    const int wid   = threadIdx.x >> 5;      // 0..7
    const int lane  = threadIdx.x & 31;
    const int d0    = lane * 8;

    const int s_base = k * ROWS_PER_CHUNK + wid * ROWS_PER_WARP;
    const float* xrow = x + ((size_t)b * SS + s_base) * DD;
    const float* mrow = mask + (size_t)b * SS + s_base;

    // ---- per-lane parameter setup (once) ----
    const float4 g1 = *(const float4*)(gamma + d0);
    const float4 g2 = *(const float4*)(gamma + d0 + 4);
    const float4 w1 = *(const float4*)(w + d0);
    const float4 w2 = *(const float4*)(w + d0 + 4);
    const float4 b1 = *(const float4*)(beta + d0);
    const float4 b2 = *(const float4*)(beta + d0 + 4);

    float gw[8];
    gw[0] = g1.x * w1.x; gw[1] = g1.y * w1.y; gw[2] = g1.z * w1.z; gw[3] = g1.w * w1.w;
    gw[4] = g2.x * w2.x; gw[5] = g2.y * w2.y; gw[6] = g2.z * w2.z; gw[7] = g2.w * w2.w;

    float sgw = gw[0]+gw[1]+gw[2]+gw[3]+gw[4]+gw[5]+gw[6]+gw[7];
    float sbw = b1.x*w1.x + b1.y*w1.y + b1.z*w1.z + b1.w*w1.w
              + b2.x*w2.x + b2.y*w2.y + b2.z*w2.z + b2.w*w2.w;
    #pragma unroll
    for (int o = 16; o > 0; o >>= 1) {
        sgw += __shfl_xor_sync(~0u, sgw, o);
        sbw += __shfl_xor_sync(~0u, sbw, o);
    }
    const float cterm = sbw + bias[0];

    // Preload this warp's 16 mask values into lanes 0..15 (off the hot path)
    const float mval = (lane < ROWS_PER_WARP) ? mrow[lane] : 0.0f;

    // ---- pipelined online softmax accumulation over 16 rows ----
    float acc[8];
    #pragma unroll
    for (int j = 0; j < 8; j++) acc[j] = 0.0f;
    float m = -INFINITY, Z = 0.0f;

    float4 xa[3], xc[3];                      // rotating row buffers
    xa[0] = *(const float4*)(xrow + d0);
    xc[0] = *(const float4*)(xrow + d0 + 4);
    xa[1] = *(const float4*)(xrow + DD + d0);
    xc[1] = *(const float4*)(xrow + DD + d0 + 4);

    // reduce row 0 (current reduction results)
    float rsx, rsx2, rsxgw;
    {
        const float4 a = xa[0], c = xc[0];
        float sx   = a.x + a.y + a.z + a.w + c.x + c.y + c.z + c.w;
        float sx2  = a.x*a.x + a.y*a.y + a.z*a.z + a.w*a.w
                   + c.x*c.x + c.y*c.y + c.z*c.z + c.w*c.w;
        float sxgw = a.x*gw[0] + a.y*gw[1] + a.z*gw[2] + a.w*gw[3]
                   + c.x*gw[4] + c.y*gw[5] + c.z*gw[6] + c.w*gw[7];
        #pragma unroll
        for (int o = 16; o > 0; o >>= 1) {
            sx   += __shfl_xor_sync(~0u, sx,   o);
            sx2  += __shfl_xor_sync(~0u, sx2,  o);
            sxgw += __shfl_xor_sync(~0u, sxgw, o);
        }
        rsx = sx; rsx2 = sx2; rsxgw = sxgw;
    }

    #pragma unroll
    for (int r = 0; r < ROWS_PER_WARP; r++) {
        // stage 1: issue loads for row r+2
        if (r + 2 < ROWS_PER_WARP) {
            xa[(r + 2) % 3] = *(const float4*)(xrow + (size_t)(r + 2) * DD + d0);
            xc[(r + 2) % 3] = *(const float4*)(xrow + (size_t)(r + 2) * DD + d0 + 4);
        }

        // stage 2: butterfly-reduce row r+1 (independent of stage 3)
        float nsx = 0.0f, nsx2 = 0.0f, nsxgw = 0.0f;
        if (r + 1 < ROWS_PER_WARP) {
            const float4 a = xa[(r + 1) % 3], c = xc[(r + 1) % 3];
            nsx   = a.x + a.y + a.z + a.w + c.x + c.y + c.z + c.w;
            nsx2  = a.x*a.x + a.y*a.y + a.z*a.z + a.w*a.w
                  + c.x*c.x + c.y*c.y + c.z*c.z + c.w*c.w;
            nsxgw = a.x*gw[0] + a.y*gw[1] + a.z*gw[2] + a.w*gw[3]
                  + c.x*gw[4] + c.y*gw[5] + c.z*gw[6] + c.w*gw[7];
            #pragma unroll
            for (int o = 16; o > 0; o >>= 1) {
                nsx   += __shfl_xor_sync(~0u, nsx,   o);
                nsx2  += __shfl_xor_sync(~0u, nsx2,  o);
                nsxgw += __shfl_xor_sync(~0u, nsxgw, o);
            }
        }

        // stage 3: score + online update for row r (uses last iter's reduction)
        {
            const float mk  = __shfl_sync(~0u, mval, r);
            const float mu  = rsx * (1.0f / DD);
            const float var = rsx2 * (1.0f / DD) - mu * mu;
            const float rs  = rsqrtf(var + 1e-3f);
            float score = rs * (rsxgw - mu * sgw) + cterm;
            score += (1.0f - mk) * -1e9f;

            // single-exp online update: one of {sc, p} is exactly 1
            const float dlt = score - m;                 // +inf on first iter
            const bool  up  = dlt > 0.0f;
            const float e   = __expf(up ? -dlt : dlt);   // exp(-|dlt|); 0 first iter
            const float sc  = up ? e : 1.0f;
            const float p   = up ? 1.0f : e;
            if (up) m = score;

            const float4 a = xa[r % 3], c = xc[r % 3];
            Z = Z * sc + p;
            acc[0] = acc[0] * sc + p * a.x;
            acc[1] = acc[1] * sc + p * a.y;
            acc[2] = acc[2] * sc + p * a.z;
            acc[3] = acc[3] * sc + p * a.w;
            acc[4] = acc[4] * sc + p * c.x;
            acc[5] = acc[5] * sc + p * c.y;
            acc[6] = acc[6] * sc + p * c.z;
            acc[7] = acc[7] * sc + p * c.w;
        }

        rsx = nsx; rsx2 = nsx2; rsxgw = nsxgw;
    }

    // ---- block-level combine of the 8 warp partials ----
    __shared__ float s_m[8];
    __shared__ float s_z[8];
    __shared__ float s_acc[8][DD];

    if (lane == 0) { s_m[wid] = m; s_z[wid] = Z; }
    __syncthreads();

    float M = s_m[0];
    #pragma unroll
    for (int t = 1; t < 8; t++) M = fmaxf(M, s_m[t]);

    const float myscale = __expf(m - M);
    #pragma unroll
    for (int j = 0; j < 8; j++) s_acc[wid][d0 + j] = acc[j] * myscale;
    __syncthreads();

    const int t = threadIdx.x;
    float asum = 0.0f;
    #pragma unroll
    for (int ww = 0; ww < 8; ww++) asum += s_acc[ww][t];
    g_acc[(size_t)chunk * DD + t] = asum;

    if (t == 0) {
        float Zb = 0.0f;
        #pragma unroll
        for (int ww = 0; ww < 8; ww++) Zb += s_z[ww] * __expf(s_m[ww] - M);
        g_m[chunk] = M;
        g_z[chunk] = Zb;
    }

    // ---- last-block-done arrival: single-thread release fence + atomic ----
    __shared__ int s_last;
    __syncthreads();                 // block stores hb-ordered before thread 0
    if (t == 0) {
        __threadfence();             // cumulative: publishes whole block's stores
        const int prev = atomicAdd(&g_cnt[b], 1);
        s_last = (prev == SPLIT - 1);
    }
    __syncthreads();
    if (!s_last) return;

    // combiner block: single-thread acquire fence, then block-wide reads
    if (t == 0) {
        g_cnt[b] = 0;                // self-reset for next graph replay
        __threadfence();             // cumulative: orders subsequent block reads
    }
    __syncthreads();

    __shared__ float c_m[SPLIT];
    __shared__ float c_z[SPLIT];
    __shared__ float c_sc[SPLIT];

    if (t < SPLIT) {
        c_m[t] = g_m[b * SPLIT + t];
        c_z[t] = g_z[b * SPLIT + t];
    }
    __syncthreads();

    float Mb = c_m[0];
    #pragma unroll
    for (int kk = 1; kk < SPLIT; kk++) Mb = fmaxf(Mb, c_m[kk]);

    if (t < SPLIT) c_sc[t] = __expf(c_m[t] - Mb);
    __syncthreads();

    // thread t owns column t: fixed-order 32-chunk combine (deterministic,
    // identical summation order kk=0..31 to the two-kernel version)
    float csum = 0.0f;
    #pragma unroll
    for (int kk = 0; kk < SPLIT; kk++)
        csum += g_acc[(size_t)(b * SPLIT + kk) * DD + t] * c_sc[kk];

    float zsum = 0.0f;
    #pragma unroll
    for (int kk = 0; kk < SPLIT; kk++) zsum += c_z[kk] * c_sc[kk];

    out[b * DD + t] = csum / zsum;
}

// ---------------------------------------------------------------------------
extern "C" void kernel_launch(void* const* d_in, const int* in_sizes, int n_in,
                              void* d_out, int out_size)
{
    const float* x     = (const float*)d_in[0];
    const float* mask  = (const float*)d_in[1];
    const float* gamma = (const float*)d_in[2];
    const float* beta  = (const float*)d_in[3];
    const float* w     = (const float*)d_in[4];
    const float* bias  = (const float*)d_in[5];
    float* out = (float*)d_out;

    fused_kernel<<<NCHUNK, 256>>>(x, mask, gamma, beta, w, bias, out);
}